// round 12
// baseline (speedup 1.0000x reference)
#include <cuda_runtime.h>
#include <math.h>
#include <stdint.h>

// DuplicateRemovalLayer: x (B,16,3) fp32 -> out (B,16,3) fp32.
// Groups [0:6),[6:9),[9:12),[12:15): object j zeroed iff ANY later object i
// in its group has dR(i,j) < 0.05; inactive objects (pt<=0) use eta=phi=1e6
// sentinels (two inactive objects ARE mutual duplicates). Index 15 passthrough.
//
// BULK-ASYNC (TMA-engine) variant: per tile, ONE 24KB cp.async.bulk load
// (global->smem, mbarrier complete_tx) and ONE 24KB cp.async.bulk store
// (smem->global, bulk_group, overlapped with next tile's compute).
// Engine-driven contiguous transfers give the DRAM scheduler long
// same-direction runs. NBUF=4 ring, prefetch distance 2, store slack 1,
// 2 blocks/SM. Smem layout is TMA-contiguous (192 B/batch, unpadded);
// compute-phase LDS.128 4-way conflicts are accepted (far from binding).

#define THREADS 128
#define BPB     128                      // batches per tile
#define FPB     48                       // floats per batch
#define TILE_BYTES (BPB * FPB * 4)       // 24576
#define NBUF    4
#define SMEM_BUFS (NBUF * TILE_BYTES)    // 98304
#define SMEM_TOTAL (SMEM_BUFS + NBUF * 8)  // + 4 mbarriers
#define BLOCKS_PER_SM 2

__device__ __forceinline__ unsigned smem_u32(const void* p) {
    return (unsigned)__cvta_generic_to_shared(p);
}

__device__ __forceinline__ void mbar_init(unsigned mbar, unsigned count) {
    asm volatile("mbarrier.init.shared.b64 [%0], %1;" :: "r"(mbar), "r"(count) : "memory");
}
__device__ __forceinline__ void mbar_expect_tx(unsigned mbar, unsigned bytes) {
    asm volatile("mbarrier.arrive.expect_tx.shared.b64 _, [%0], %1;"
                 :: "r"(mbar), "r"(bytes) : "memory");
}
__device__ __forceinline__ void mbar_wait_parity(unsigned mbar, unsigned parity) {
    asm volatile(
        "{\n\t"
        ".reg .pred P;\n\t"
        "WAIT_%=:\n\t"
        "mbarrier.try_wait.parity.shared.b64 P, [%0], %1;\n\t"
        "@P bra DONE_%=;\n\t"
        "bra WAIT_%=;\n\t"
        "DONE_%=:\n\t"
        "}"
        :: "r"(mbar), "r"(parity) : "memory");
}
__device__ __forceinline__ void bulk_load(void* sdst, const void* gsrc,
                                          unsigned bytes, unsigned mbar) {
    asm volatile(
        "cp.async.bulk.shared::cluster.global.mbarrier::complete_tx::bytes "
        "[%0], [%1], %2, [%3];"
        :: "r"(smem_u32(sdst)), "l"(gsrc), "r"(bytes), "r"(mbar) : "memory");
}
__device__ __forceinline__ void bulk_store(void* gdst, const void* ssrc, unsigned bytes) {
    asm volatile("cp.async.bulk.global.shared::cta.bulk_group [%0], [%1], %2;"
                 :: "l"(gdst), "r"(smem_u32(ssrc)), "r"(bytes) : "memory");
    asm volatile("cp.async.bulk.commit_group;" ::: "memory");
}
#define BULK_WAIT_READ1() asm volatile("cp.async.bulk.wait_group.read 1;" ::: "memory")
#define BULK_WAIT_ALL()   asm volatile("cp.async.bulk.wait_group 0;" ::: "memory")
#define FENCE_ASYNC()     asm volatile("fence.proxy.async.shared::cta;" ::: "memory")

__device__ __forceinline__ bool is_dup(float ei, float pi_, float ej, float pj) {
    const float TWOPI  = 6.28318530717958647692f;
    const float INV2PI = 0.15915494309189533577f;
    float deta = ei - ej;
    float d    = pi_ - pj;
    float dphi = fmaf(-TWOPI, rintf(d * INV2PI), d);   // wrapped; enters squared
    return fmaf(deta, deta, dphi * dphi) < 0.0025f;    // dr^2 < 0.05^2
}

template <int N>
__device__ __forceinline__ void remove_group(const float* E, const float* P,
                                             unsigned& keep, int s0) {
    #pragma unroll
    for (int i = 1; i < N; i++) {
        #pragma unroll
        for (int j = 0; j < i; j++) {
            if (is_dup(E[s0 + i], P[s0 + i], E[s0 + j], P[s0 + j]))
                keep &= ~(1u << (s0 + j));
        }
    }
}

__global__ __launch_bounds__(THREADS)
void dup_removal_kernel(const float* __restrict__ in, float* __restrict__ out,
                        int B, int ntiles) {
    extern __shared__ char smem[];
    char* buf[NBUF];
    #pragma unroll
    for (int j = 0; j < NBUF; j++) buf[j] = smem + j * TILE_BYTES;
    unsigned mbar0 = smem_u32(smem + SMEM_BUFS);

    const int tid = threadIdx.x;
    const int G = gridDim.x;
    const int bid = blockIdx.x;

    if (tid == 0) {
        #pragma unroll
        for (int j = 0; j < NBUF; j++) mbar_init(mbar0 + j * 8, 1);
    }
    __syncthreads();

    // helper lambda-ish: tile index for loop counter li
    // tile(li) = bid + li*G ; bytes(li) = min(BPB, B - tile*BPB) * 192

    // Prologue: issue loads for li = 0, 1
    if (tid == 0) {
        #pragma unroll
        for (int li0 = 0; li0 < 2; li0++) {
            int tile = bid + li0 * G;
            if (tile < ntiles) {
                unsigned bytes = (unsigned)(min(BPB, B - tile * BPB) * (FPB * 4));
                mbar_expect_tx(mbar0 + (li0 % NBUF) * 8, bytes);
                bulk_load(buf[li0 % NBUF],
                          (const char*)in + (long long)tile * TILE_BYTES, bytes,
                          mbar0 + (li0 % NBUF) * 8);
            }
        }
    }

    int li = 0;
    for (int tile = bid; tile < ntiles; tile += G, li++) {
        char* cur = buf[li % NBUF];
        const int nvalid = min(BPB, B - tile * BPB);
        const unsigned bytes = (unsigned)(nvalid * (FPB * 4));

        // Issue load for li+2 (into buffer stored at li-2; store-read drained
        // by wait_group.read 1 — only tid0 commits groups, per-thread order ok).
        if (tid == 0) {
            BULK_WAIT_READ1();
            int tile2 = tile + 2 * G;
            if (tile2 < ntiles) {
                int jb = (li + 2) % NBUF;
                unsigned bytes2 = (unsigned)(min(BPB, B - tile2 * BPB) * (FPB * 4));
                mbar_expect_tx(mbar0 + jb * 8, bytes2);
                bulk_load(buf[jb], (const char*)in + (long long)tile2 * TILE_BYTES,
                          bytes2, mbar0 + jb * 8);
            }
        }

        // Wait for current tile's load (mbar reused every NBUF iters)
        mbar_wait_parity(mbar0 + (li % NBUF) * 8, (unsigned)((li >> 2) & 1));

        // ---- compute: one thread per batch; sparse zero write-back ----
        if (tid < nvalid) {
            const float4* pb = (const float4*)(cur + tid * (FPB * 4));
            float p[FPB];
            #pragma unroll
            for (int k = 0; k < FPB / 4; k++) {      // 12 LDS.128 (4-way conflicted, cheap)
                float4 v = pb[k];
                p[4*k] = v.x; p[4*k+1] = v.y; p[4*k+2] = v.z; p[4*k+3] = v.w;
            }

            float E[15], P[15];
            #pragma unroll
            for (int i = 0; i < 15; i++) {
                bool act = p[3*i] > 0.0f;
                E[i] = act ? p[3*i+1] : 1000000.0f;
                P[i] = act ? p[3*i+2] : 1000000.0f;
            }

            unsigned keep = 0x7FFFu;
            remove_group<6>(E, P, keep, 0);
            remove_group<3>(E, P, keep, 6);
            remove_group<3>(E, P, keep, 9);
            remove_group<3>(E, P, keep, 12);

            if (keep != 0x7FFFu) {
                float* ps = (float*)(cur + tid * (FPB * 4));
                #pragma unroll
                for (int i = 0; i < 15; i++) {
                    if (!(keep & (1u << i))) {
                        ps[3*i] = 0.0f; ps[3*i+1] = 0.0f; ps[3*i+2] = 0.0f;
                    }
                }
            }
        }

        // Order generic-proxy smem writes before the async-proxy bulk store
        FENCE_ASYNC();
        __syncthreads();

        if (tid == 0)
            bulk_store((char*)out + (long long)tile * TILE_BYTES, cur, bytes);
        // No trailing barrier: other threads don't touch cur again; tid0's
        // wait_group.read next iteration gates buffer reuse.
    }

    // Guarantee all bulk stores are globally visible before kernel exit.
    if (tid == 0) BULK_WAIT_ALL();
}

extern "C" void kernel_launch(void* const* d_in, const int* in_sizes, int n_in,
                              void* d_out, int out_size) {
    const float* x = (const float*)d_in[0];
    float* out = (float*)d_out;
    const int B = in_sizes[0] / FPB;
    const int ntiles = (B + BPB - 1) / BPB;

    cudaFuncSetAttribute(dup_removal_kernel,
                         cudaFuncAttributeMaxDynamicSharedMemorySize, SMEM_TOTAL);

    int dev = 0, nsm = 148;
    cudaGetDevice(&dev);
    cudaDeviceGetAttribute(&nsm, cudaDevAttrMultiProcessorCount, dev);

    int grid = BLOCKS_PER_SM * nsm;     // 2 blocks/SM
    if (grid > ntiles) grid = ntiles;

    dup_removal_kernel<<<grid, THREADS, SMEM_TOTAL>>>(x, out, B, ntiles);
}